// round 16
// baseline (speedup 1.0000x reference)
#include <cuda_runtime.h>
#include <cuda_bf16.h>

#define WARPS_PER_BLOCK 8
#define NT 32
#define MC 4
#define NITER_MAX 64
#define LOG2E 1.4426950408889634f

union f2u { float2 f; unsigned long long u; };

static __device__ __forceinline__ float2 fma2(float2 a, float2 b, float2 c) {
    f2u A, Bv, C, D; A.f = a; Bv.f = b; C.f = c;
    asm("fma.rn.f32x2 %0, %1, %2, %3;" : "=l"(D.u) : "l"(A.u), "l"(Bv.u), "l"(C.u));
    return D.f;
}
static __device__ __forceinline__ float2 mul2(float2 a, float2 b) {
    f2u A, Bv, D; A.f = a; Bv.f = b;
    asm("mul.rn.f32x2 %0, %1, %2;" : "=l"(D.u) : "l"(A.u), "l"(Bv.u));
    return D.f;
}
static __device__ __forceinline__ float2 add2(float2 a, float2 b) {
    f2u A, Bv, D; A.f = a; Bv.f = b;
    asm("add.rn.f32x2 %0, %1, %2;" : "=l"(D.u) : "l"(A.u), "l"(Bv.u));
    return D.f;
}
static __device__ __forceinline__ float rcp_fast(float x) {
    float r; asm("rcp.approx.f32 %0, %1;" : "=f"(r) : "f"(x)); return r;
}
static __device__ __forceinline__ float ex2_fast(float x) {
    float r; asm("ex2.approx.f32 %0, %1;" : "=f"(r) : "f"(x)); return r;
}

// One warp per batch element. Quad-split HH ownership with PERMUTED row
// slots: lane (m = lane&7, q = lane>>3) holds cols [8q,8q+8) of rows
// {lane, lane^16, lane^8, lane^24} (slots 0..3). This makes the xHH
// reduce-scatter select-free: S0=P0+shfl(P2,8); S1=P1+shfl(P3,8);
// acc=S0+shfl(S1,16) lands on row=lane.
__global__ void __launch_bounds__(WARPS_PER_BLOCK * 32, 4)
cmdnet_kernel(const float* __restrict__ yt,
              const float* __restrict__ Ht,
              const float* __restrict__ sigmat0,
              const float* __restrict__ m_c,
              const float* __restrict__ alpha,
              const float* __restrict__ taui,
              const float* __restrict__ delta,
              float* __restrict__ out,
              int B, int NR, int NITER)
{
    __shared__ __align__(16) float4 s_lasc[NITER_MAX];  // la_j * scale_it * log2e
    __shared__ __align__(16) float4 s_p1[NITER_MAX];    // {-sc, -sc, -ta, d*log2e}
    __shared__ float s_la[MC];
    __shared__ float s_tauN, s_tauNl2;
    __shared__ __align__(16) float s_stage[2][WARPS_PER_BLOCK][2][NT];
    __shared__ __align__(16) float s_xt[2][WARPS_PER_BLOCK][NT];

    const int tid   = threadIdx.x;
    const int wslot = tid >> 5;
    const int lane  = tid & 31;
    const int q     = lane >> 3;        // column-quad

    if (tid < NITER) {
        float ta = fabsf(taui[tid]);
        float scale_raw = (tid == 0) ? 1.0f : ta;     // first_iter softmax scale = 1
        float sc = scale_raw * LOG2E;
        float4 l;
        l.x = logf(alpha[0]) * sc;
        l.y = logf(alpha[1]) * sc;
        l.z = logf(alpha[2]) * sc;
        l.w = logf(alpha[3]) * sc;
        s_lasc[tid] = l;
        s_p1[tid] = make_float4(-scale_raw, -scale_raw, -ta, delta[tid] * LOG2E);
    }
    if (tid < MC) s_la[tid] = logf(alpha[tid]);
    if (tid == 0) {
        float tn = fabsf(taui[NITER]);
        s_tauN   = tn;
        s_tauNl2 = tn * LOG2E;
    }
    __syncthreads();

    const int b = blockIdx.x * WARPS_PER_BLOCK + wslot;
    if (b >= B) return;

    const float* Hb = Ht + (size_t)b * NR * NT;
    const float* yb = yt + (size_t)b * NR;

    // Permuted row slots: slot0=own row (lane), then xor 16, 8, 24.
    const int rows0 = lane;
    const int rows1 = lane ^ 16;
    const int rows2 = lane ^ 8;
    const int rows3 = lane ^ 24;

    // ---------------- Phase 1: quad-split HH + per-row yH ----------------
    // hhq[j][c] = HH[rows_j][8q+2c .. 8q+2c+1]; double-buffered stage ->
    // one syncwarp per 2-row group (WAR separated by intervening sync).
    float2 hhq[4][4];
    #pragma unroll
    for (int j = 0; j < 4; j++)
        #pragma unroll
        for (int c = 0; c < 4; c++) hhq[j][c] = make_float2(0.0f, 0.0f);
    float yH = 0.0f;

    for (int g = 0; g < NR / 2; g++) {
        const int r0  = g * 2;
        const int buf = g & 1;
        float h0 = Hb[(r0 + 0) * NT + lane];             // own column (coalesced)
        float h1 = Hb[(r0 + 1) * NT + lane];
        s_stage[buf][wslot][0][lane] = h0;
        s_stage[buf][wslot][1][lane] = h1;
        yH = fmaf(yb[r0 + 0], h0, yH);                   // row = lane
        yH = fmaf(yb[r0 + 1], h1, yH);
        __syncwarp();
        #pragma unroll
        for (int rr = 0; rr < 2; rr++) {
            float4 va = *reinterpret_cast<const float4*>(&s_stage[buf][wslot][rr][8 * q]);
            float4 vb = *reinterpret_cast<const float4*>(&s_stage[buf][wslot][rr][8 * q + 4]);
            // conflict-free gathers: address sets are lane^{0,16,8,24} bijections
            float hr0 = s_stage[buf][wslot][rr][rows0];
            float hr1 = s_stage[buf][wslot][rr][rows1];
            float hr2 = s_stage[buf][wslot][rr][rows2];
            float hr3 = s_stage[buf][wslot][rr][rows3];
            const float2 A0 = make_float2(va.x, va.y);
            const float2 A1 = make_float2(va.z, va.w);
            const float2 A2 = make_float2(vb.x, vb.y);
            const float2 A3 = make_float2(vb.z, vb.w);
            float2 H0 = make_float2(hr0, hr0);
            float2 H1 = make_float2(hr1, hr1);
            float2 H2 = make_float2(hr2, hr2);
            float2 H3 = make_float2(hr3, hr3);
            hhq[0][0] = fma2(H0, A0, hhq[0][0]);
            hhq[0][1] = fma2(H0, A1, hhq[0][1]);
            hhq[0][2] = fma2(H0, A2, hhq[0][2]);
            hhq[0][3] = fma2(H0, A3, hhq[0][3]);
            hhq[1][0] = fma2(H1, A0, hhq[1][0]);
            hhq[1][1] = fma2(H1, A1, hhq[1][1]);
            hhq[1][2] = fma2(H1, A2, hhq[1][2]);
            hhq[1][3] = fma2(H1, A3, hhq[1][3]);
            hhq[2][0] = fma2(H2, A0, hhq[2][0]);
            hhq[2][1] = fma2(H2, A1, hhq[2][1]);
            hhq[2][2] = fma2(H2, A2, hhq[2][2]);
            hhq[2][3] = fma2(H2, A3, hhq[2][3]);
            hhq[3][0] = fma2(H3, A0, hhq[3][0]);
            hhq[3][1] = fma2(H3, A1, hhq[3][1]);
            hhq[3][2] = fma2(H3, A2, hhq[3][2]);
            hhq[3][3] = fma2(H3, A3, hhq[3][3]);
        }
    }

    // ---------------- Phase 2: 64 iterations ----------------
    float2 m2[2];
    m2[0] = make_float2(m_c[0], m_c[1]);
    m2[1] = make_float2(m_c[2], m_c[3]);

    float2 Gn2[2] = {make_float2(0.f, 0.f), make_float2(0.f, 0.f)}; // -G*log2e
    float sig2;
    { float s = sigmat0[b]; sig2 = s * s; }
    const float2 sig2_2  = make_float2(sig2, sig2);
    const float2 nsig2_2 = make_float2(-sig2, -sig2);

    float e0, e1, e2, e3;
    float inv = 0.0f, xt = 0.0f;

    #pragma unroll 2
    for (int it = 0; it < NITER; it++) {
        const float4 lasc = s_lasc[it];
        const float4 p    = s_p1[it];     // {-sc, -sc, -ta, d*log2e}
        const float2 sc2  = make_float2(p.x, p.y);
        const int buf = it & 1;

        // barrier term first (depends only on loop-carried Gn)
        const float2 eg0 = make_float2(ex2_fast(Gn2[0].x), ex2_fast(Gn2[0].y)); // exp(-G)
        const float2 eg1 = make_float2(ex2_fast(Gn2[1].x), ex2_fast(Gn2[1].y));
        float2 t0 = fma2(nsig2_2, eg0, sig2_2);
        float2 t1 = fma2(nsig2_2, eg1, sig2_2);

        // max-free softmax in log2 domain
        float2 z0 = fma2(sc2, Gn2[0], make_float2(lasc.x, lasc.y));
        float2 z1 = fma2(sc2, Gn2[1], make_float2(lasc.z, lasc.w));
        e0 = ex2_fast(z0.x); e1 = ex2_fast(z0.y);
        e2 = ex2_fast(z1.x); e3 = ex2_fast(z1.y);
        float sum = (e0 + e1) + (e2 + e3);
        inv = rcp_fast(sum);

        float em = e0 * m2[0].x;
        em = fmaf(e1, m2[0].y, em);
        em = fmaf(e2, m2[1].x, em);
        em = fmaf(e3, m2[1].y, em);
        xt = em * inv;                   // soft symbol for row = lane

        // share xt, then quad-split dot: 2 LDS.128 + 16 FFMA2 + butterfly
        s_xt[buf][wslot][lane] = xt;
        __syncwarp();
        float4 v0 = *reinterpret_cast<const float4*>(&s_xt[buf][wslot][8 * q]);
        float4 v1 = *reinterpret_cast<const float4*>(&s_xt[buf][wslot][8 * q + 4]);
        const float2 x0 = make_float2(v0.x, v0.y);
        const float2 x1 = make_float2(v0.z, v0.w);
        const float2 x2 = make_float2(v1.x, v1.y);
        const float2 x3 = make_float2(v1.z, v1.w);
        float P[4];
        #pragma unroll
        for (int j = 0; j < 4; j++) {
            float2 a = mul2(x0, hhq[j][0]);
            a = fma2(x1, hhq[j][1], a);
            a = fma2(x2, hhq[j][2], a);
            a = fma2(x3, hhq[j][3], a);
            P[j] = a.x + a.y;            // partial dot of row rows_j over my 8 cols
        }
        // select-free reduce-scatter:
        // stage 1 (xor 8): my slots {2,3} are partner's slots {0,1} rows
        float S0 = P[0] + __shfl_xor_sync(0xFFFFFFFFu, P[2], 8);   // row lane
        float S1 = P[1] + __shfl_xor_sync(0xFFFFFFFFu, P[3], 8);   // row lane^16
        // stage 2 (xor 16): partner's S1 is my row
        float acc = S0 + __shfl_xor_sync(0xFFFFFFFFu, S1, 16);     // row = lane

        // grad_L_j = t_j + ci * e_j*(m_j - xt),  ci = ta*(xHH-yH)*inv
        const float c  = (yH - acc) * p.z;       // = ta*(acc - yH)
        const float ci = c * inv;
        const float2 ci2  = make_float2(ci, ci);
        const float2 dl2  = make_float2(p.w, p.w);
        const float2 nxt2 = make_float2(-xt, -xt);
        float2 d0 = add2(m2[0], nxt2);
        float2 d1 = add2(m2[1], nxt2);
        float2 w0 = mul2(make_float2(e0, e1), d0);
        float2 w1 = mul2(make_float2(e2, e3), d1);
        float2 g0 = fma2(ci2, w0, t0);
        float2 g1 = fma2(ci2, w1, t1);
        Gn2[0] = fma2(dl2, g0, Gn2[0]);
        Gn2[1] = fma2(dl2, g1, Gn2[1]);
    }

    // ---------------- Final layer: max-free softmax + soft symbol ------------
    float f[MC];
    {
        const float tl2 = s_tauNl2, tn = s_tauN;
        const float2 ntn2 = make_float2(-tn, -tn);
        float2 z0 = fma2(ntn2, Gn2[0], make_float2(s_la[0] * tl2, s_la[1] * tl2));
        float2 z1 = fma2(ntn2, Gn2[1], make_float2(s_la[2] * tl2, s_la[3] * tl2));
        e0 = ex2_fast(z0.x); e1 = ex2_fast(z0.y);
        e2 = ex2_fast(z1.x); e3 = ex2_fast(z1.y);
        float sum = (e0 + e1) + (e2 + e3);
        float iv = __fdividef(1.0f, sum);
        f[0] = e0 * iv; f[1] = e1 * iv; f[2] = e2 * iv; f[3] = e3 * iv;
        float em = f[0] * m2[0].x;
        em = fmaf(f[1], m2[0].y, em);
        em = fmaf(f[2], m2[1].x, em);
        em = fmaf(f[3], m2[1].y, em);
        xt = em;
    }

    // ---------------- Write out: ft [B,NT,MC] then xt [B,NT] ----------------
    const size_t base = (size_t)b * NT + lane;
    float4 o;
    o.x = f[0]; o.y = f[1]; o.z = f[2]; o.w = f[3];
    *reinterpret_cast<float4*>(&out[base * MC]) = o;
    out[(size_t)B * NT * MC + base] = xt;
}

extern "C" void kernel_launch(void* const* d_in, const int* in_sizes, int n_in,
                              void* d_out, int out_size)
{
    const float* yt     = (const float*)d_in[0];
    const float* Ht     = (const float*)d_in[1];
    const float* sig    = (const float*)d_in[2];
    const float* m      = (const float*)d_in[3];
    const float* alpha  = (const float*)d_in[4];
    const float* taui   = (const float*)d_in[5];
    const float* delta  = (const float*)d_in[6];

    const int B     = in_sizes[2];
    const int NR    = in_sizes[0] / B;
    const int NITER = in_sizes[6];

    const int blocks = (B + WARPS_PER_BLOCK - 1) / WARPS_PER_BLOCK;
    cmdnet_kernel<<<blocks, WARPS_PER_BLOCK * 32>>>(
        yt, Ht, sig, m, alpha, taui, delta, (float*)d_out, B, NR, NITER);
}

// round 17
// speedup vs baseline: 1.0108x; 1.0108x over previous
#include <cuda_runtime.h>
#include <cuda_bf16.h>

#define WARPS_PER_BLOCK 8
#define NT 32
#define MC 4
#define NITER_MAX 64
#define LOG2E 1.4426950408889634f

union f2u { float2 f; unsigned long long u; };

static __device__ __forceinline__ float2 fma2(float2 a, float2 b, float2 c) {
    f2u A, Bv, C, D; A.f = a; Bv.f = b; C.f = c;
    asm("fma.rn.f32x2 %0, %1, %2, %3;" : "=l"(D.u) : "l"(A.u), "l"(Bv.u), "l"(C.u));
    return D.f;
}
static __device__ __forceinline__ float2 mul2(float2 a, float2 b) {
    f2u A, Bv, D; A.f = a; Bv.f = b;
    asm("mul.rn.f32x2 %0, %1, %2;" : "=l"(D.u) : "l"(A.u), "l"(Bv.u));
    return D.f;
}
static __device__ __forceinline__ float2 add2(float2 a, float2 b) {
    f2u A, Bv, D; A.f = a; Bv.f = b;
    asm("add.rn.f32x2 %0, %1, %2;" : "=l"(D.u) : "l"(A.u), "l"(Bv.u));
    return D.f;
}
static __device__ __forceinline__ float rcp_fast(float x) {
    float r; asm("rcp.approx.f32 %0, %1;" : "=f"(r) : "f"(x)); return r;
}
static __device__ __forceinline__ float ex2_fast(float x) {
    float r; asm("ex2.approx.f32 %0, %1;" : "=f"(r) : "f"(x)); return r;
}

// One warp per batch element. Quad-split HH ownership with PERMUTED row
// slots: lane (q = lane>>3) holds cols [8q,8q+8) of rows
// {lane, lane^16, lane^8, lane^24} (slots 0..3) -> select-free
// reduce-scatter: S0=P0+shfl(P2,8); S1=P1+shfl(P3,8); acc=S0+shfl(S1,16).
__global__ void __launch_bounds__(WARPS_PER_BLOCK * 32, 4)
cmdnet_kernel(const float* __restrict__ yt,
              const float* __restrict__ Ht,
              const float* __restrict__ sigmat0,
              const float* __restrict__ m_c,
              const float* __restrict__ alpha,
              const float* __restrict__ taui,
              const float* __restrict__ delta,
              float* __restrict__ out,
              int B, int NR, int NITER)
{
    __shared__ __align__(16) float4 s_lasc[NITER_MAX];  // la_j * scale_it * log2e
    __shared__ __align__(16) float4 s_p1[NITER_MAX];    // {-sc, -sc, -ta, d*log2e}
    __shared__ float s_la[MC];
    __shared__ float s_tauN, s_tauNl2;
    __shared__ __align__(16) float s_stage[2][WARPS_PER_BLOCK][2][NT];
    __shared__ __align__(16) float s_xt[2][WARPS_PER_BLOCK][NT];

    const int tid   = threadIdx.x;
    const int wslot = tid >> 5;
    const int lane  = tid & 31;
    const int q     = lane >> 3;        // column-quad

    if (tid < NITER) {
        float ta = fabsf(taui[tid]);
        float scale_raw = (tid == 0) ? 1.0f : ta;     // first_iter softmax scale = 1
        float sc = scale_raw * LOG2E;
        float4 l;
        l.x = logf(alpha[0]) * sc;
        l.y = logf(alpha[1]) * sc;
        l.z = logf(alpha[2]) * sc;
        l.w = logf(alpha[3]) * sc;
        s_lasc[tid] = l;
        s_p1[tid] = make_float4(-scale_raw, -scale_raw, -ta, delta[tid] * LOG2E);
    }
    if (tid < MC) s_la[tid] = logf(alpha[tid]);
    if (tid == 0) {
        float tn = fabsf(taui[NITER]);
        s_tauN   = tn;
        s_tauNl2 = tn * LOG2E;
    }
    __syncthreads();

    const int b = blockIdx.x * WARPS_PER_BLOCK + wslot;
    if (b >= B) return;

    const float* Hb = Ht + (size_t)b * NR * NT;
    const float* yb = yt + (size_t)b * NR;

    // Permuted row slots: slot0 = own row (lane); others xor 16, 8, 24.
    const int rows1 = lane ^ 16;
    const int rows2 = lane ^ 8;
    const int rows3 = lane ^ 24;

    // ---------------- Phase 1: quad-split HH + per-row yH ----------------
    // hhq[j][c] = HH[rows_j][8q+2c .. 8q+2c+1]; double-buffered stage ->
    // one syncwarp per 2-row group. Own-row gather (slot 0) reuses h0/h1
    // already in registers (no LDS).
    float2 hhq[4][4];
    #pragma unroll
    for (int j = 0; j < 4; j++)
        #pragma unroll
        for (int c = 0; c < 4; c++) hhq[j][c] = make_float2(0.0f, 0.0f);
    float yH = 0.0f;

    for (int g = 0; g < NR / 2; g++) {
        const int r0  = g * 2;
        const int buf = g & 1;
        float h0 = Hb[(r0 + 0) * NT + lane];             // own column (coalesced)
        float h1 = Hb[(r0 + 1) * NT + lane];
        s_stage[buf][wslot][0][lane] = h0;
        s_stage[buf][wslot][1][lane] = h1;
        yH = fmaf(yb[r0 + 0], h0, yH);                   // row = lane
        yH = fmaf(yb[r0 + 1], h1, yH);
        __syncwarp();
        #pragma unroll
        for (int rr = 0; rr < 2; rr++) {
            const float hown = (rr == 0) ? h0 : h1;      // slot 0 row = lane
            float4 va = *reinterpret_cast<const float4*>(&s_stage[buf][wslot][rr][8 * q]);
            float4 vb = *reinterpret_cast<const float4*>(&s_stage[buf][wslot][rr][8 * q + 4]);
            float hr1 = s_stage[buf][wslot][rr][rows1];  // conflict-free bijections
            float hr2 = s_stage[buf][wslot][rr][rows2];
            float hr3 = s_stage[buf][wslot][rr][rows3];
            const float2 A0 = make_float2(va.x, va.y);
            const float2 A1 = make_float2(va.z, va.w);
            const float2 A2 = make_float2(vb.x, vb.y);
            const float2 A3 = make_float2(vb.z, vb.w);
            float2 H0 = make_float2(hown, hown);
            float2 H1 = make_float2(hr1, hr1);
            float2 H2 = make_float2(hr2, hr2);
            float2 H3 = make_float2(hr3, hr3);
            hhq[0][0] = fma2(H0, A0, hhq[0][0]);
            hhq[0][1] = fma2(H0, A1, hhq[0][1]);
            hhq[0][2] = fma2(H0, A2, hhq[0][2]);
            hhq[0][3] = fma2(H0, A3, hhq[0][3]);
            hhq[1][0] = fma2(H1, A0, hhq[1][0]);
            hhq[1][1] = fma2(H1, A1, hhq[1][1]);
            hhq[1][2] = fma2(H1, A2, hhq[1][2]);
            hhq[1][3] = fma2(H1, A3, hhq[1][3]);
            hhq[2][0] = fma2(H2, A0, hhq[2][0]);
            hhq[2][1] = fma2(H2, A1, hhq[2][1]);
            hhq[2][2] = fma2(H2, A2, hhq[2][2]);
            hhq[2][3] = fma2(H2, A3, hhq[2][3]);
            hhq[3][0] = fma2(H3, A0, hhq[3][0]);
            hhq[3][1] = fma2(H3, A1, hhq[3][1]);
            hhq[3][2] = fma2(H3, A2, hhq[3][2]);
            hhq[3][3] = fma2(H3, A3, hhq[3][3]);
        }
    }

    // ---------------- Phase 2: 64 iterations ----------------
    float2 m2[2];
    m2[0] = make_float2(m_c[0], m_c[1]);
    m2[1] = make_float2(m_c[2], m_c[3]);

    float2 Gn2[2] = {make_float2(0.f, 0.f), make_float2(0.f, 0.f)}; // -G*log2e
    float sig2;
    { float s = sigmat0[b]; sig2 = s * s; }
    const float2 sig2_2  = make_float2(sig2, sig2);
    const float2 nsig2_2 = make_float2(-sig2, -sig2);

    float e0, e1, e2, e3;
    float inv = 0.0f, xt = 0.0f;

    #pragma unroll 4
    for (int it = 0; it < NITER; it++) {
        const float4 lasc = s_lasc[it];
        const float4 p    = s_p1[it];     // {-sc, -sc, -ta, d*log2e}
        const float2 sc2  = make_float2(p.x, p.y);
        const int buf = it & 1;

        // barrier term first (depends only on loop-carried Gn)
        const float2 eg0 = make_float2(ex2_fast(Gn2[0].x), ex2_fast(Gn2[0].y)); // exp(-G)
        const float2 eg1 = make_float2(ex2_fast(Gn2[1].x), ex2_fast(Gn2[1].y));
        float2 t0 = fma2(nsig2_2, eg0, sig2_2);
        float2 t1 = fma2(nsig2_2, eg1, sig2_2);

        // max-free softmax in log2 domain
        float2 z0 = fma2(sc2, Gn2[0], make_float2(lasc.x, lasc.y));
        float2 z1 = fma2(sc2, Gn2[1], make_float2(lasc.z, lasc.w));
        e0 = ex2_fast(z0.x); e1 = ex2_fast(z0.y);
        e2 = ex2_fast(z1.x); e3 = ex2_fast(z1.y);
        float sum = (e0 + e1) + (e2 + e3);
        inv = rcp_fast(sum);

        float em = e0 * m2[0].x;
        em = fmaf(e1, m2[0].y, em);
        em = fmaf(e2, m2[1].x, em);
        em = fmaf(e3, m2[1].y, em);
        xt = em * inv;                   // soft symbol for row = lane

        // share xt, then quad-split dot: 2 LDS.128 + 16 FFMA2 + butterfly
        s_xt[buf][wslot][lane] = xt;
        __syncwarp();
        float4 v0 = *reinterpret_cast<const float4*>(&s_xt[buf][wslot][8 * q]);
        float4 v1 = *reinterpret_cast<const float4*>(&s_xt[buf][wslot][8 * q + 4]);
        const float2 x0 = make_float2(v0.x, v0.y);
        const float2 x1 = make_float2(v0.z, v0.w);
        const float2 x2 = make_float2(v1.x, v1.y);
        const float2 x3 = make_float2(v1.z, v1.w);
        float P[4];
        #pragma unroll
        for (int j = 0; j < 4; j++) {
            float2 a = mul2(x0, hhq[j][0]);
            a = fma2(x1, hhq[j][1], a);
            a = fma2(x2, hhq[j][2], a);
            a = fma2(x3, hhq[j][3], a);
            P[j] = a.x + a.y;            // partial dot of row rows_j over my 8 cols
        }
        // select-free reduce-scatter
        float S0 = P[0] + __shfl_xor_sync(0xFFFFFFFFu, P[2], 8);   // row lane
        float S1 = P[1] + __shfl_xor_sync(0xFFFFFFFFu, P[3], 8);   // row lane^16
        float acc = S0 + __shfl_xor_sync(0xFFFFFFFFu, S1, 16);     // row = lane

        // grad_L_j = t_j + ci * e_j*(m_j - xt),  ci = ta*(xHH-yH)*inv
        const float c  = (yH - acc) * p.z;       // = ta*(acc - yH)
        const float ci = c * inv;
        const float2 ci2  = make_float2(ci, ci);
        const float2 dl2  = make_float2(p.w, p.w);
        const float2 nxt2 = make_float2(-xt, -xt);
        float2 d0 = add2(m2[0], nxt2);
        float2 d1 = add2(m2[1], nxt2);
        float2 w0 = mul2(make_float2(e0, e1), d0);
        float2 w1 = mul2(make_float2(e2, e3), d1);
        float2 g0 = fma2(ci2, w0, t0);
        float2 g1 = fma2(ci2, w1, t1);
        Gn2[0] = fma2(dl2, g0, Gn2[0]);
        Gn2[1] = fma2(dl2, g1, Gn2[1]);
    }

    // ---------------- Final layer: max-free softmax + soft symbol ------------
    float f[MC];
    {
        const float tl2 = s_tauNl2, tn = s_tauN;
        const float2 ntn2 = make_float2(-tn, -tn);
        float2 z0 = fma2(ntn2, Gn2[0], make_float2(s_la[0] * tl2, s_la[1] * tl2));
        float2 z1 = fma2(ntn2, Gn2[1], make_float2(s_la[2] * tl2, s_la[3] * tl2));
        e0 = ex2_fast(z0.x); e1 = ex2_fast(z0.y);
        e2 = ex2_fast(z1.x); e3 = ex2_fast(z1.y);
        float sum = (e0 + e1) + (e2 + e3);
        float iv = __fdividef(1.0f, sum);
        f[0] = e0 * iv; f[1] = e1 * iv; f[2] = e2 * iv; f[3] = e3 * iv;
        float em = f[0] * m2[0].x;
        em = fmaf(f[1], m2[0].y, em);
        em = fmaf(f[2], m2[1].x, em);
        em = fmaf(f[3], m2[1].y, em);
        xt = em;
    }

    // ---------------- Write out: ft [B,NT,MC] then xt [B,NT] ----------------
    const size_t base = (size_t)b * NT + lane;
    float4 o;
    o.x = f[0]; o.y = f[1]; o.z = f[2]; o.w = f[3];
    *reinterpret_cast<float4*>(&out[base * MC]) = o;
    out[(size_t)B * NT * MC + base] = xt;
}

extern "C" void kernel_launch(void* const* d_in, const int* in_sizes, int n_in,
                              void* d_out, int out_size)
{
    const float* yt     = (const float*)d_in[0];
    const float* Ht     = (const float*)d_in[1];
    const float* sig    = (const float*)d_in[2];
    const float* m      = (const float*)d_in[3];
    const float* alpha  = (const float*)d_in[4];
    const float* taui   = (const float*)d_in[5];
    const float* delta  = (const float*)d_in[6];

    const int B     = in_sizes[2];
    const int NR    = in_sizes[0] / B;
    const int NITER = in_sizes[6];

    const int blocks = (B + WARPS_PER_BLOCK - 1) / WARPS_PER_BLOCK;
    cmdnet_kernel<<<blocks, WARPS_PER_BLOCK * 32>>>(
        yt, Ht, sig, m, alpha, taui, delta, (float*)d_out, B, NR, NITER);
}